// round 15
// baseline (speedup 1.0000x reference)
#include <cuda_runtime.h>
#include <cstdint>
#include <cstddef>

#define FDIM 128
#define NMAX 100000
#define EMAX 1700000
#define NCLS 40
#define SCAN_BLK 256

static __device__ float g_x1[(size_t)NMAX * FDIM];
static __device__ float g_x2[(size_t)NMAX * FDIM];
static __device__ int   g_deg[NMAX];
static __device__ int   g_rowptr[NMAX];
static __device__ int   g_cursor[NMAX];
static __device__ int   g_csr[EMAX];
static __device__ int   g_bsum[1024];
static __device__ int   g_boff[1024];

// ---------------------------------------------------------------------------
// CSR build
// ---------------------------------------------------------------------------
__global__ void zero_int_kernel(int* __restrict__ p, int n) {
    int i = blockIdx.x * blockDim.x + threadIdx.x;
    if (i < n) p[i] = 0;
}

__global__ void hist_kernel(const int* __restrict__ dst, int* __restrict__ deg, int E) {
    int e = blockIdx.x * blockDim.x + threadIdx.x;
    if (e < E) atomicAdd(deg + __ldg(dst + e), 1);
}

__global__ void bsum_kernel(const int* __restrict__ deg, int* __restrict__ bsum, int N) {
    __shared__ int s[SCAN_BLK];
    int i = blockIdx.x * SCAN_BLK + threadIdx.x;
    int v = (i < N) ? deg[i] : 0;
    s[threadIdx.x] = v;
    __syncthreads();
    for (int off = SCAN_BLK / 2; off > 0; off >>= 1) {
        if (threadIdx.x < off) s[threadIdx.x] += s[threadIdx.x + off];
        __syncthreads();
    }
    if (threadIdx.x == 0) bsum[blockIdx.x] = s[0];
}

__global__ void scan_bsum_kernel(const int* __restrict__ bsum, int* __restrict__ boff, int NB) {
    __shared__ int s[1024];
    int t = threadIdx.x;
    int v = (t < NB) ? bsum[t] : 0;
    s[t] = v;
    __syncthreads();
    for (int off = 1; off < 1024; off <<= 1) {
        int x = (t >= off) ? s[t - off] : 0;
        __syncthreads();
        s[t] += x;
        __syncthreads();
    }
    boff[t] = s[t] - v;
}

__global__ void scan_final_kernel(const int* __restrict__ deg, const int* __restrict__ boff,
                                  int* __restrict__ rowptr, int* __restrict__ cursor, int N) {
    __shared__ int s[SCAN_BLK];
    int i = blockIdx.x * SCAN_BLK + threadIdx.x;
    int t = threadIdx.x;
    int v = (i < N) ? deg[i] : 0;
    s[t] = v;
    __syncthreads();
    for (int off = 1; off < SCAN_BLK; off <<= 1) {
        int x = (t >= off) ? s[t - off] : 0;
        __syncthreads();
        s[t] += x;
        __syncthreads();
    }
    if (i < N) {
        int r = boff[blockIdx.x] + s[t] - v;
        rowptr[i] = r;
        cursor[i] = r;
    }
}

__global__ void fill_kernel(const int* __restrict__ src, const int* __restrict__ dst,
                            int* __restrict__ cursor, int* __restrict__ csr, int E) {
    int e = blockIdx.x * blockDim.x + threadIdx.x;
    if (e < E) {
        int pos = atomicAdd(cursor + __ldg(dst + e), 1);
        csr[pos] = __ldg(src + e);
    }
}

// ---------------------------------------------------------------------------
// Fused GraphConv layer: C = relu( (sum_{j in N(i)} Xin[j]) @ Wrel
//                               + Xin @ Wroot + bias )
// Phase 1: root GEMM (LDG double-buffered smem, tf32 mma)
// Phase 2: CSR gather of this CTA's 128 rows into fp32 smem tile (aliasing As)
// Phase 3: rel GEMM, A fragments straight from the smem tile (LDS + cvt)
// ---------------------------------------------------------------------------
#define KS_STRIDE 136          // tf32 staging stride  (== 8 mod 32)
#define AG_STRIDE 132          // fp32 agg tile stride (== 4 mod 32)
#define SMEM_FUSED ((128 * AG_STRIDE + 2 * 16 * KS_STRIDE) * 4)

__device__ __forceinline__ uint32_t f2tf32(float f) {
    uint32_t r;
    asm("cvt.rna.tf32.f32 %0, %1;" : "=r"(r) : "f"(f));
    return r;
}

__global__ __launch_bounds__(256, 2)
void gc_fused(const float* __restrict__ Xin,
              const float* __restrict__ Wrel, const float* __restrict__ Wroot,
              const float* __restrict__ bias,
              const int* __restrict__ rowptr, const int* __restrict__ deg,
              const int* __restrict__ csr,
              float* __restrict__ C, int M) {
    extern __shared__ unsigned char dynsh[];
    float*    aggF = (float*)dynsh;                                   // [128][132]
    uint32_t* AsB  = (uint32_t*)dynsh;                                // alias, 2x[16][136]
    uint32_t* BsB  = (uint32_t*)(dynsh + 128 * AG_STRIDE * 4);        // 2x[16][136]

    const int tid  = threadIdx.x;
    const int lane = tid & 31;
    const int g    = lane >> 2;
    const int t    = lane & 3;
    const int warp = tid >> 5;
    const int wm   = (warp >> 2) * 64;
    const int wn   = (warp & 3) * 32;
    const int m0   = blockIdx.x * 128;

    float acc[4][4][4];
#pragma unroll
    for (int mi = 0; mi < 4; mi++)
#pragma unroll
        for (int ni = 0; ni < 4; ni++)
#pragma unroll
            for (int j = 0; j < 4; j++) acc[mi][ni][j] = 0.f;

    float4 ra[2], rb[2];

#define AS(BUF, IDX) AsB[(BUF) * 16 * KS_STRIDE + (IDX)]
#define BS(BUF, IDX) BsB[(BUF) * 16 * KS_STRIDE + (IDX)]

#define LDG_ROOT(T) do {                                                        \
    const int kt = (T) * 16;                                                    \
    _Pragma("unroll")                                                           \
    for (int i = 0; i < 2; i++) {                                               \
        int idx  = tid + i * 256;                                               \
        int row  = idx >> 2;                                                    \
        int colq = idx & 3;                                                     \
        ra[i] = make_float4(0.f, 0.f, 0.f, 0.f);                                \
        if (m0 + row < M)                                                       \
            ra[i] = *(const float4*)(Xin + (size_t)(m0 + row) * FDIM + kt + colq * 4); \
        int k   = idx >> 5;                                                     \
        int n4  = idx & 31;                                                     \
        rb[i] = *(const float4*)(Wroot + (size_t)(kt + k) * FDIM + n4 * 4);     \
    }                                                                           \
} while (0)

#define STS_ROOT(BUF) do {                                                      \
    _Pragma("unroll")                                                           \
    for (int i = 0; i < 2; i++) {                                               \
        int idx  = tid + i * 256;                                               \
        int row  = idx >> 2;                                                    \
        int colq = idx & 3;                                                     \
        AS(BUF, (colq * 4 + 0) * KS_STRIDE + row) = f2tf32(ra[i].x);            \
        AS(BUF, (colq * 4 + 1) * KS_STRIDE + row) = f2tf32(ra[i].y);            \
        AS(BUF, (colq * 4 + 2) * KS_STRIDE + row) = f2tf32(ra[i].z);            \
        AS(BUF, (colq * 4 + 3) * KS_STRIDE + row) = f2tf32(ra[i].w);            \
        int k  = idx >> 5;                                                      \
        int n4 = idx & 31;                                                      \
        uint4 u;                                                                \
        u.x = f2tf32(rb[i].x); u.y = f2tf32(rb[i].y);                           \
        u.z = f2tf32(rb[i].z); u.w = f2tf32(rb[i].w);                           \
        *(uint4*)&BS(BUF, k * KS_STRIDE + n4 * 4) = u;                          \
    }                                                                           \
} while (0)

#define LDG_REL_B(T) do {                                                       \
    const int kt = (T) * 16;                                                    \
    _Pragma("unroll")                                                           \
    for (int i = 0; i < 2; i++) {                                               \
        int idx = tid + i * 256;                                                \
        int k   = idx >> 5;                                                     \
        int n4  = idx & 31;                                                     \
        rb[i] = *(const float4*)(Wrel + (size_t)(kt + k) * FDIM + n4 * 4);      \
    }                                                                           \
} while (0)

#define STS_REL_B(BUF) do {                                                     \
    _Pragma("unroll")                                                           \
    for (int i = 0; i < 2; i++) {                                               \
        int idx = tid + i * 256;                                                \
        int k   = idx >> 5;                                                     \
        int n4  = idx & 31;                                                     \
        uint4 u;                                                                \
        u.x = f2tf32(rb[i].x); u.y = f2tf32(rb[i].y);                           \
        u.z = f2tf32(rb[i].z); u.w = f2tf32(rb[i].w);                           \
        *(uint4*)&BS(BUF, k * KS_STRIDE + n4 * 4) = u;                          \
    }                                                                           \
} while (0)

#define MMA_TILE(AF, BF, ACC)                                                   \
    asm volatile(                                                               \
        "mma.sync.aligned.m16n8k8.row.col.f32.tf32.tf32.f32 "                   \
        "{%0,%1,%2,%3}, {%4,%5,%6,%7}, {%8,%9}, {%0,%1,%2,%3};"                 \
        : "+f"((ACC)[0]), "+f"((ACC)[1]), "+f"((ACC)[2]), "+f"((ACC)[3])        \
        : "r"((AF)[0]), "r"((AF)[1]), "r"((AF)[2]), "r"((AF)[3]),               \
          "r"((BF)[0]), "r"((BF)[1]))

#define COMPUTE_ROOT(BUF) do {                                                  \
    _Pragma("unroll")                                                           \
    for (int ks = 0; ks < 2; ks++) {                                            \
        uint32_t af[4][4];                                                      \
        uint32_t bf[4][2];                                                      \
        _Pragma("unroll")                                                       \
        for (int mi = 0; mi < 4; mi++) {                                        \
            int mb = wm + mi * 16;                                              \
            af[mi][0] = AS(BUF, (ks * 8 + t    ) * KS_STRIDE + mb + g    );     \
            af[mi][1] = AS(BUF, (ks * 8 + t    ) * KS_STRIDE + mb + g + 8);     \
            af[mi][2] = AS(BUF, (ks * 8 + t + 4) * KS_STRIDE + mb + g    );     \
            af[mi][3] = AS(BUF, (ks * 8 + t + 4) * KS_STRIDE + mb + g + 8);     \
        }                                                                       \
        _Pragma("unroll")                                                       \
        for (int ni = 0; ni < 4; ni++) {                                        \
            int nb = wn + ni * 8;                                               \
            bf[ni][0] = BS(BUF, (ks * 8 + t    ) * KS_STRIDE + nb + g);         \
            bf[ni][1] = BS(BUF, (ks * 8 + t + 4) * KS_STRIDE + nb + g);         \
        }                                                                       \
        _Pragma("unroll")                                                       \
        for (int mi = 0; mi < 4; mi++)                                          \
        _Pragma("unroll")                                                       \
        for (int ni = 0; ni < 4; ni++)                                          \
            MMA_TILE(af[mi], bf[ni], acc[mi][ni]);                              \
    }                                                                           \
} while (0)

#define COMPUTE_REL(BUF, KC) do {                                               \
    _Pragma("unroll")                                                           \
    for (int ks = 0; ks < 2; ks++) {                                            \
        const int kk = (KC) * 16 + ks * 8;                                      \
        uint32_t af[4][4];                                                      \
        uint32_t bf[4][2];                                                      \
        _Pragma("unroll")                                                       \
        for (int mi = 0; mi < 4; mi++) {                                        \
            int mb = wm + mi * 16;                                              \
            af[mi][0] = f2tf32(aggF[(mb + g    ) * AG_STRIDE + kk + t    ]);    \
            af[mi][1] = f2tf32(aggF[(mb + g + 8) * AG_STRIDE + kk + t    ]);    \
            af[mi][2] = f2tf32(aggF[(mb + g    ) * AG_STRIDE + kk + t + 4]);    \
            af[mi][3] = f2tf32(aggF[(mb + g + 8) * AG_STRIDE + kk + t + 4]);    \
        }                                                                       \
        _Pragma("unroll")                                                       \
        for (int ni = 0; ni < 4; ni++) {                                        \
            int nb = wn + ni * 8;                                               \
            bf[ni][0] = BS(BUF, (ks * 8 + t    ) * KS_STRIDE + nb + g);         \
            bf[ni][1] = BS(BUF, (ks * 8 + t + 4) * KS_STRIDE + nb + g);         \
        }                                                                       \
        _Pragma("unroll")                                                       \
        for (int mi = 0; mi < 4; mi++)                                          \
        _Pragma("unroll")                                                       \
        for (int ni = 0; ni < 4; ni++)                                          \
            MMA_TILE(af[mi], bf[ni], acc[mi][ni]);                              \
    }                                                                           \
} while (0)

    // ---- Phase 1: root GEMM (A = Xin rows, B = Wroot) ----
    LDG_ROOT(0);
    STS_ROOT(0);
    __syncthreads();
    for (int tch = 0; tch < 8; tch++) {
        const int buf = tch & 1;
        if (tch < 7) LDG_ROOT(tch + 1);
        COMPUTE_ROOT(buf);
        if (tch < 7) {
            STS_ROOT(buf ^ 1);
        }
        __syncthreads();   // also separates phase 1 from the aggF overwrite
    }

    // ---- Phase 2: CSR gather into aggF (aliases As region) ----
    {
        for (int i = 0; i < 16; i++) {
            int ml   = warp * 16 + i;
            int node = m0 + ml;
            float4 acc4 = make_float4(0.f, 0.f, 0.f, 0.f);
            if (node < M) {
                int start = __ldg(rowptr + node);
                int end   = start + __ldg(deg + node);
                int p = start;
                for (; p + 8 <= end; p += 8) {
                    int j0 = __ldg(csr + p);
                    int j1 = __ldg(csr + p + 1);
                    int j2 = __ldg(csr + p + 2);
                    int j3 = __ldg(csr + p + 3);
                    int j4 = __ldg(csr + p + 4);
                    int j5 = __ldg(csr + p + 5);
                    int j6 = __ldg(csr + p + 6);
                    int j7 = __ldg(csr + p + 7);
                    float4 v0 = *(const float4*)(Xin + (size_t)j0 * FDIM + lane * 4);
                    float4 v1 = *(const float4*)(Xin + (size_t)j1 * FDIM + lane * 4);
                    float4 v2 = *(const float4*)(Xin + (size_t)j2 * FDIM + lane * 4);
                    float4 v3 = *(const float4*)(Xin + (size_t)j3 * FDIM + lane * 4);
                    float4 v4 = *(const float4*)(Xin + (size_t)j4 * FDIM + lane * 4);
                    float4 v5 = *(const float4*)(Xin + (size_t)j5 * FDIM + lane * 4);
                    float4 v6 = *(const float4*)(Xin + (size_t)j6 * FDIM + lane * 4);
                    float4 v7 = *(const float4*)(Xin + (size_t)j7 * FDIM + lane * 4);
                    acc4.x += (v0.x + v1.x) + (v2.x + v3.x) + (v4.x + v5.x) + (v6.x + v7.x);
                    acc4.y += (v0.y + v1.y) + (v2.y + v3.y) + (v4.y + v5.y) + (v6.y + v7.y);
                    acc4.z += (v0.z + v1.z) + (v2.z + v3.z) + (v4.z + v5.z) + (v6.z + v7.z);
                    acc4.w += (v0.w + v1.w) + (v2.w + v3.w) + (v4.w + v5.w) + (v6.w + v7.w);
                }
                for (; p < end; ++p) {
                    int j = __ldg(csr + p);
                    float4 v = *(const float4*)(Xin + (size_t)j * FDIM + lane * 4);
                    acc4.x += v.x; acc4.y += v.y; acc4.z += v.z; acc4.w += v.w;
                }
            }
            *(float4*)(aggF + (size_t)ml * AG_STRIDE + lane * 4) = acc4;
        }
    }
    __syncthreads();

    // ---- Phase 3: rel GEMM (A = aggF smem, B = Wrel) ----
    LDG_REL_B(0);
    STS_REL_B(0);
    __syncthreads();
    for (int tch = 0; tch < 8; tch++) {
        const int buf = tch & 1;
        if (tch < 7) LDG_REL_B(tch + 1);
        COMPUTE_REL(buf, tch);
        if (tch < 7) {
            STS_REL_B(buf ^ 1);
            __syncthreads();
        }
    }

#undef LDG_ROOT
#undef STS_ROOT
#undef LDG_REL_B
#undef STS_REL_B
#undef COMPUTE_ROOT
#undef COMPUTE_REL
#undef AS
#undef BS

    // ---- Epilogue: bias + relu + store ----
    float2 bb[4];
#pragma unroll
    for (int ni = 0; ni < 4; ni++) {
        int col = wn + ni * 8 + t * 2;
        bb[ni].x = __ldg(bias + col);
        bb[ni].y = __ldg(bias + col + 1);
    }
#pragma unroll
    for (int mi = 0; mi < 4; mi++) {
        int row0 = m0 + wm + mi * 16 + g;
        int row1 = row0 + 8;
#pragma unroll
        for (int ni = 0; ni < 4; ni++) {
            int col = wn + ni * 8 + t * 2;
            if (row0 < M) {
                float2 v;
                v.x = fmaxf(acc[mi][ni][0] + bb[ni].x, 0.f);
                v.y = fmaxf(acc[mi][ni][1] + bb[ni].y, 0.f);
                *(float2*)(C + (size_t)row0 * FDIM + col) = v;
            }
            if (row1 < M) {
                float2 v;
                v.x = fmaxf(acc[mi][ni][2] + bb[ni].x, 0.f);
                v.y = fmaxf(acc[mi][ni][3] + bb[ni].y, 0.f);
                *(float2*)(C + (size_t)row1 * FDIM + col) = v;
            }
        }
    }
}

// ---------------------------------------------------------------------------
// Head as TF32 mma GEMM with fused log_softmax epilogue. (unchanged)
// ---------------------------------------------------------------------------
#define HBK 32
#define HAS_STRIDE 36
#define HEAD_SMEM_BYTES ((256 * NCLS + 128 * HAS_STRIDE + NCLS) * 4)

__global__ __launch_bounds__(256)
void head_gemm(const float* __restrict__ x1, const float* __restrict__ x2,
               const float* __restrict__ Wl, const float* __restrict__ bl,
               float* __restrict__ out, int N) {
    extern __shared__ uint32_t sh[];
    uint32_t* Bs  = sh;
    uint32_t* As2 = sh + 256 * NCLS;
    float*    bs  = (float*)(As2 + 128 * HAS_STRIDE);

    const int tid  = threadIdx.x;
    const int lane = tid & 31;
    const int g    = lane >> 2;
    const int t    = lane & 3;
    const int warp = tid >> 5;
    const int wrow = warp * 16;
    const int m0   = blockIdx.x * 128;

    for (int i = tid; i < 256 * NCLS; i += 256) Bs[i] = f2tf32(__ldg(Wl + i));
    if (tid < NCLS) bs[tid] = __ldg(bl + tid);

    float acc[5][4];
#pragma unroll
    for (int ni = 0; ni < 5; ni++)
#pragma unroll
        for (int j = 0; j < 4; j++) acc[ni][j] = 0.f;

    for (int kc = 0; kc < 8; kc++) {
        const float* src = (kc < 4) ? x1 : x2;
        const int kb = (kc & 3) * HBK;
        __syncthreads();
#pragma unroll
        for (int i = 0; i < 4; i++) {
            int idx = tid + i * 256;
            int row = idx >> 3;
            int q   = idx & 7;
            float4 v = make_float4(0.f, 0.f, 0.f, 0.f);
            if (m0 + row < N)
                v = *(const float4*)(src + (size_t)(m0 + row) * FDIM + kb + q * 4);
            uint32_t* ap = &As2[row * HAS_STRIDE + q * 4];
            ap[0] = f2tf32(v.x); ap[1] = f2tf32(v.y);
            ap[2] = f2tf32(v.z); ap[3] = f2tf32(v.w);
        }
        __syncthreads();

#pragma unroll
        for (int ks = 0; ks < 4; ks++) {
            uint32_t af[4];
            af[0] = As2[(wrow + g    ) * HAS_STRIDE + ks * 8 + t    ];
            af[1] = As2[(wrow + g + 8) * HAS_STRIDE + ks * 8 + t    ];
            af[2] = As2[(wrow + g    ) * HAS_STRIDE + ks * 8 + t + 4];
            af[3] = As2[(wrow + g + 8) * HAS_STRIDE + ks * 8 + t + 4];
            const int kg = kc * HBK + ks * 8;
#pragma unroll
            for (int ni = 0; ni < 5; ni++) {
                uint32_t b0 = Bs[(kg + t    ) * NCLS + ni * 8 + g];
                uint32_t b1 = Bs[(kg + t + 4) * NCLS + ni * 8 + g];
                asm volatile(
                    "mma.sync.aligned.m16n8k8.row.col.f32.tf32.tf32.f32 "
                    "{%0,%1,%2,%3}, {%4,%5,%6,%7}, {%8,%9}, {%0,%1,%2,%3};"
                    : "+f"(acc[ni][0]), "+f"(acc[ni][1]),
                      "+f"(acc[ni][2]), "+f"(acc[ni][3])
                    : "r"(af[0]), "r"(af[1]), "r"(af[2]), "r"(af[3]),
                      "r"(b0), "r"(b1));
            }
        }
    }

    float la[10], lb[10];
#pragma unroll
    for (int ni = 0; ni < 5; ni++) {
        float b0 = bs[ni * 8 + t * 2];
        float b1 = bs[ni * 8 + t * 2 + 1];
        la[ni * 2]     = acc[ni][0] + b0;
        la[ni * 2 + 1] = acc[ni][1] + b1;
        lb[ni * 2]     = acc[ni][2] + b0;
        lb[ni * 2 + 1] = acc[ni][3] + b1;
    }
    float mA = la[0], mB = lb[0];
#pragma unroll
    for (int c = 1; c < 10; c++) { mA = fmaxf(mA, la[c]); mB = fmaxf(mB, lb[c]); }
    mA = fmaxf(mA, __shfl_xor_sync(0xffffffffu, mA, 1));
    mA = fmaxf(mA, __shfl_xor_sync(0xffffffffu, mA, 2));
    mB = fmaxf(mB, __shfl_xor_sync(0xffffffffu, mB, 1));
    mB = fmaxf(mB, __shfl_xor_sync(0xffffffffu, mB, 2));
    float sA = 0.f, sB = 0.f;
#pragma unroll
    for (int c = 0; c < 10; c++) { sA += expf(la[c] - mA); sB += expf(lb[c] - mB); }
    sA += __shfl_xor_sync(0xffffffffu, sA, 1);
    sA += __shfl_xor_sync(0xffffffffu, sA, 2);
    sB += __shfl_xor_sync(0xffffffffu, sB, 1);
    sB += __shfl_xor_sync(0xffffffffu, sB, 2);
    float oA = mA + logf(sA);
    float oB = mB + logf(sB);

    int rowA = m0 + wrow + g;
    int rowB = rowA + 8;
#pragma unroll
    for (int ni = 0; ni < 5; ni++) {
        int col = ni * 8 + t * 2;
        if (rowA < N) {
            float2 v; v.x = la[ni * 2] - oA; v.y = la[ni * 2 + 1] - oA;
            *(float2*)(out + (size_t)rowA * NCLS + col) = v;
        }
        if (rowB < N) {
            float2 v; v.x = lb[ni * 2] - oB; v.y = lb[ni * 2 + 1] - oB;
            *(float2*)(out + (size_t)rowB * NCLS + col) = v;
        }
    }
}

// ---------------------------------------------------------------------------
// kernel_launch
// ---------------------------------------------------------------------------
extern "C" void kernel_launch(void* const* d_in, const int* in_sizes, int n_in,
                              void* d_out, int out_size) {
    const float* x    = (const float*)d_in[0];
    const int*   ei   = (const int*)d_in[1];
    const float* Wr1  = (const float*)d_in[2];
    const float* b1   = (const float*)d_in[3];
    const float* Wt1  = (const float*)d_in[4];
    const float* Wr2  = (const float*)d_in[5];
    const float* b2   = (const float*)d_in[6];
    const float* Wt2  = (const float*)d_in[7];
    const float* Wl   = (const float*)d_in[8];
    const float* bl   = (const float*)d_in[9];
    float*       out  = (float*)d_out;

    const int N = in_sizes[0] / FDIM;
    const int E = in_sizes[1] / 2;
    const int* src = ei;
    const int* dst = ei + E;

    float *x1, *x2;
    int *deg, *rowptr, *cursor, *csr, *bsum, *boff;
    cudaGetSymbolAddress((void**)&x1,     g_x1);
    cudaGetSymbolAddress((void**)&x2,     g_x2);
    cudaGetSymbolAddress((void**)&deg,    g_deg);
    cudaGetSymbolAddress((void**)&rowptr, g_rowptr);
    cudaGetSymbolAddress((void**)&cursor, g_cursor);
    cudaGetSymbolAddress((void**)&csr,    g_csr);
    cudaGetSymbolAddress((void**)&bsum,   g_bsum);
    cudaGetSymbolAddress((void**)&boff,   g_boff);

    static int attr_done = 0;
    if (!attr_done) {
        cudaFuncSetAttribute(gc_fused, cudaFuncAttributeMaxDynamicSharedMemorySize,
                             SMEM_FUSED);
        cudaFuncSetAttribute(head_gemm, cudaFuncAttributeMaxDynamicSharedMemorySize,
                             HEAD_SMEM_BYTES);
        attr_done = 1;
    }

    const int NB      = (N + SCAN_BLK - 1) / SCAN_BLK;
    const int edgeBlk = (E + 255) / 256;
    const int nodeBlk = (N + 255) / 256;
    const int gemmBlk = (N + 127) / 128;

    // ---- CSR build (once, reused by both layers) ----
    zero_int_kernel<<<nodeBlk, 256>>>(deg, N);
    hist_kernel<<<edgeBlk, 256>>>(dst, deg, E);
    bsum_kernel<<<NB, SCAN_BLK>>>(deg, bsum, N);
    scan_bsum_kernel<<<1, 1024>>>(bsum, boff, NB);
    scan_final_kernel<<<NB, SCAN_BLK>>>(deg, boff, rowptr, cursor, N);
    fill_kernel<<<edgeBlk, 256>>>(src, dst, cursor, csr, E);

    // ---- Layer 1 (fused gather + GEMM) ----
    gc_fused<<<gemmBlk, 256, SMEM_FUSED>>>(x, Wr1, Wt1, b1, rowptr, deg, csr, x1, N);

    // ---- Layer 2 (fused gather + GEMM) ----
    gc_fused<<<gemmBlk, 256, SMEM_FUSED>>>(x1, Wr2, Wt2, b2, rowptr, deg, csr, x2, N);

    // ---- Head (fused GEMM + log_softmax) ----
    head_gemm<<<gemmBlk, 256, HEAD_SMEM_BYTES>>>(x1, x2, Wl, bl, out, N);
}